// round 15
// baseline (speedup 1.0000x reference)
#include <cuda_runtime.h>
#include <cuda.h>
#include <cuda_fp16.h>
#include <math.h>
#include <stdint.h>

#define Bsz   8
#define Tlen  2048
#define Cdim  1024
#define Edim  4096
#define Mtot  (Bsz * Tlen)       // 16384 tokens
#define CHUNK 32
#define NCHUNK (Tlen / CHUNK)    // 64
#define BHALF (Bsz / 2)          // 4 batches per pipeline
#define MHALF (Mtot / 2)         // 8192 rows per pipeline

typedef __half f16;

// ---------------- scratch (no cudaMalloc allowed) ----------------
__device__ __align__(16) f16   g_out1[(size_t)Mtot * Cdim];   // gate*x (fp16 residual)
__device__ __align__(16) float g_csum[Bsz * NCHUNK * Cdim];   // chunk aggregates
__device__ __align__(16) int   g_flag[Bsz * NCHUNK];          // aggregate-published flags
__device__ __align__(16) float g_ssqp[(size_t)Mtot * 8];      // per-row ssq partials (8 slabs)

__device__ __align__(16) f16 g_s  [(size_t)Mtot * Cdim];   // state (fp16)
__device__ __align__(16) f16 g_act[(size_t)Mtot * Edim];   // relu hidden (fp16)

// transposed weights: [N, K] K-major fp16
__device__ __align__(16) f16 g_w1T [Cdim * Cdim];
__device__ __align__(16) f16 g_w2aT[(size_t)Edim * Cdim];  // includes n2w fold
__device__ __align__(16) f16 g_w2bT[(size_t)Cdim * Edim];

// ---------------- helpers ----------------
__device__ __forceinline__ uint32_t smem_u32(const void* p) {
    uint32_t a;
    asm("{ .reg .u64 t; cvta.to.shared.u64 t, %1; cvt.u32.u64 %0, t; }" : "=r"(a) : "l"(p));
    return a;
}
__device__ __forceinline__ void cp16(uint32_t s, const void* g) {
    asm volatile("cp.async.cg.shared.global [%0], [%1], 16;" :: "r"(s), "l"(g) : "memory");
}
#define CP_COMMIT() asm volatile("cp.async.commit_group;" ::: "memory")
#define CP_WAIT(n)  asm volatile("cp.async.wait_group %0;" :: "n"(n) : "memory")

#define LDSM_X4(r, addr) \
    asm volatile("ldmatrix.sync.aligned.m8n8.x4.shared.b16 {%0,%1,%2,%3}, [%4];" \
        : "=r"((r)[0]), "=r"((r)[1]), "=r"((r)[2]), "=r"((r)[3]) : "r"(addr))

#define MMA_F16(d, a, b0, b1) \
    asm volatile("mma.sync.aligned.m16n8k16.row.col.f32.f16.f16.f32 " \
        "{%0,%1,%2,%3}, {%4,%5,%6,%7}, {%8,%9}, {%0,%1,%2,%3};" \
        : "+f"((d)[0]), "+f"((d)[1]), "+f"((d)[2]), "+f"((d)[3]) \
        : "r"((a)[0]), "r"((a)[1]), "r"((a)[2]), "r"((a)[3]), "r"(b0), "r"(b1))

// ---------------- fused rmsnorm1 + full scan (decoupled lookback) ----------------
#define SCAN_SMEM (65536 + 32768)   // ys 32x1024 f16 (64KB) + sacc 8x1024 f32 (32KB)

__global__ void __launch_bounds__(256) scan_fused(const float* __restrict__ x,
                                                  const float* __restrict__ w,
                                                  int b0)
{
    extern __shared__ __align__(16) char sm[];
    f16*   ys   = reinterpret_cast<f16*>(sm);            // [32][1024]
    float* sacc = reinterpret_cast<float*>(sm + 65536);  // [8][1024]

    int ch = blockIdx.x, b = b0 + blockIdx.y;
    int tid = threadIdx.x, wid = tid >> 5, lane = tid & 31;
    int R0 = b * Tlen + ch * CHUNK;

    float4 acc[8];
    #pragma unroll
    for (int j = 0; j < 8; j++) acc[j] = make_float4(0.f, 0.f, 0.f, 0.f);

    #pragma unroll
    for (int r = 0; r < 4; r++) {
        int rloc = wid * 4 + r;
        const float4* xr = reinterpret_cast<const float4*>(x) + (size_t)(R0 + rloc) * (Cdim / 4);
        float4 v[8];
        #pragma unroll
        for (int j = 0; j < 8; j++) v[j] = xr[lane + 32 * j];
        float ss = 0.f;
        #pragma unroll
        for (int j = 0; j < 8; j++)
            ss += v[j].x * v[j].x + v[j].y * v[j].y + v[j].z * v[j].z + v[j].w * v[j].w;
        #pragma unroll
        for (int o = 16; o; o >>= 1) ss += __shfl_xor_sync(0xffffffffu, ss, o);
        float inv = rsqrtf(ss * (1.0f / Cdim) + 1e-6f);

        #pragma unroll
        for (int j = 0; j < 8; j++) {
            float4 wv = reinterpret_cast<const float4*>(w)[lane + 32 * j];
            __half2 ha, hb;
            ha.x = __float2half(v[j].x * inv * wv.x);
            ha.y = __float2half(v[j].y * inv * wv.y);
            hb.x = __float2half(v[j].z * inv * wv.z);
            hb.y = __float2half(v[j].w * inv * wv.w);
            uint2 pk;
            pk.x = *reinterpret_cast<const unsigned*>(&ha);
            pk.y = *reinterpret_cast<const unsigned*>(&hb);
            *reinterpret_cast<uint2*>(ys + (size_t)rloc * Cdim + (lane + 32 * j) * 4) = pk;
            float2 fa = __half22float2(ha), fb = __half22float2(hb);
            acc[j].x += fa.x; acc[j].y += fa.y; acc[j].z += fb.x; acc[j].w += fb.y;
        }
    }

    #pragma unroll
    for (int j = 0; j < 8; j++)
        *reinterpret_cast<float4*>(&sacc[wid * 1024 + (lane + 32 * j) * 4]) = acc[j];
    __syncthreads();
    float4 aggv = make_float4(0.f, 0.f, 0.f, 0.f);
    #pragma unroll
    for (int w8 = 0; w8 < 8; w8++) {
        float4 t = *reinterpret_cast<const float4*>(&sacc[w8 * 1024 + tid * 4]);
        aggv.x += t.x; aggv.y += t.y; aggv.z += t.z; aggv.w += t.w;
    }

    float4* csum4 = reinterpret_cast<float4*>(g_csum);
    csum4[(size_t)(b * NCHUNK + ch) * 256 + tid] = aggv;
    __threadfence();
    __syncthreads();
    if (tid == 0) atomicExch(&g_flag[b * NCHUNK + ch], 1);

    float4 run = make_float4(0.f, 0.f, 0.f, 0.f);
    if (ch > 0) {
        volatile int* fl = (volatile int*)(g_flag + b * NCHUNK);
        bool all;
        do {
            bool mine = (tid < ch) ? (fl[tid] != 0) : true;
            all = __syncthreads_and(mine);
        } while (!all);
        __threadfence();
        const float4* aggp = csum4 + (size_t)b * NCHUNK * 256 + tid;
        for (int j = 0; j < ch; j++) {
            float4 a;
            const float4* p = aggp + (size_t)j * 256;
            asm volatile("ld.global.cg.v4.f32 {%0,%1,%2,%3}, [%4];"
                         : "=f"(a.x), "=f"(a.y), "=f"(a.z), "=f"(a.w) : "l"(p));
            run.x += a.x; run.y += a.y; run.z += a.z; run.w += a.w;
        }
    }

    int tg0 = ch * CHUNK;
    #pragma unroll
    for (int t = 0; t < CHUNK; t++) {
        uint2 pk = *reinterpret_cast<const uint2*>(ys + (size_t)t * Cdim + tid * 4);
        __half2 ha = *reinterpret_cast<const __half2*>(&pk.x);
        __half2 hb = *reinterpret_cast<const __half2*>(&pk.y);
        float2 fa = __half22float2(ha), fb = __half22float2(hb);
        run.x += fa.x; run.y += fa.y; run.z += fb.x; run.w += fb.y;
        float tg = (float)(tg0 + t);
        float rs = 1.0f / (0.5f * (tg + 1.f) * (tg + 2.f));
        __half2 o0, o1;
        o0.x = __float2half(run.x * rs); o0.y = __float2half(run.y * rs);
        o1.x = __float2half(run.z * rs); o1.y = __float2half(run.w * rs);
        uint2 ow;
        ow.x = *reinterpret_cast<const unsigned*>(&o0);
        ow.y = *reinterpret_cast<const unsigned*>(&o1);
        *reinterpret_cast<uint2*>(g_s + (size_t)(R0 + t) * Cdim + tid * 4) = ow;
    }
}

// ---------------- weight transposes (side stream) ----------------
__device__ __forceinline__ void transpose_tile(const float* __restrict__ in,
                                               f16* __restrict__ o16,
                                               const float* __restrict__ scale,
                                               int K, int N, int bx, int by, float* sh)
{
    int k0 = bx * 32, n0 = by * 32;
    int x = threadIdx.x & 31, y = threadIdx.x >> 5;
    #pragma unroll
    for (int i = y; i < 32; i += 8)
        sh[i * 33 + x] = in[(size_t)(k0 + i) * N + n0 + x];
    __syncthreads();
    float sc = scale ? scale[k0 + x] : 1.0f;
    #pragma unroll
    for (int i = y; i < 32; i += 8)
        o16[(size_t)(n0 + i) * K + k0 + x] = __float2half(sh[x * 33 + i] * sc);
}

#define TW1  (Cdim / 32) * (Cdim / 32)   // 1024
#define TW2A (Cdim / 32) * (Edim / 32)   // 4096
#define TW2B (Edim / 32) * (Cdim / 32)   // 4096

__global__ void __launch_bounds__(256) trans_kernel(const float* __restrict__ w1,
                                                    const float* __restrict__ w2a,
                                                    const float* __restrict__ n2w,
                                                    const float* __restrict__ w2b)
{
    __shared__ float sh[32 * 33];
    int bid = blockIdx.x;
    if (bid < TW1)  { transpose_tile(w1,  g_w1T,  nullptr, Cdim, Cdim, bid & 31, bid >> 5, sh); return; }
    bid -= TW1;
    if (bid < TW2A) { transpose_tile(w2a, g_w2aT, n2w, Cdim, Edim, bid & 31, bid >> 5, sh); return; }
    bid -= TW2A;
    transpose_tile(w2b, g_w2bT, nullptr, Edim, Cdim, bid & 127, bid >> 7, sh);
}

// ---------------- fp16 HMMA GEMM: 128x128x64, 3-stage cp.async, hoisted-addr reg dbuf ----
#define BKt    64
#define STG    3
#define TILEB  32768
#define SMTOT  (STG * TILEB)

__device__ __forceinline__ void load_tile64(const f16* __restrict__ A,
                                            const f16* __restrict__ B,
                                            int bm, int bn, int koff, int K,
                                            uint32_t sbase, int stage, int tid)
{
    uint32_t sA = sbase + stage * TILEB;
    uint32_t sB = sA + 16384;
    #pragma unroll
    for (int i = 0; i < 4; i++) {
        int idx = tid + i * 256;
        int row = idx >> 3, ch = idx & 7;
        int chs = ch ^ (row & 7);
        uint32_t so = (uint32_t)(row * 128 + chs * 16);
        cp16(sA + so, A + (size_t)(bm + row) * K + koff + ch * 8);
        cp16(sB + so, B + (size_t)(bn + row) * K + koff + ch * 8);
    }
}

template<int EPI>
__global__ void __launch_bounds__(256, 2) mma_gemm(
    const f16* __restrict__ Ag, const f16* __restrict__ Bg,
    const float* __restrict__ bias,
    const float* __restrict__ auxF, const f16* __restrict__ auxH,
    float* __restrict__ outF, f16* __restrict__ outH,
    int N, int K, int bmOff)
{
    extern __shared__ __align__(16) char smem[];
    uint32_t sbase = smem_u32(smem);
    int tid = threadIdx.x, wid = tid >> 5, lane = tid & 31;
    int bm = bmOff + blockIdx.y * 128, bn = blockIdx.x * 128;
    int wm = (wid >> 2) * 64, wn = (wid & 3) * 32;

    int nkt = K / BKt;

    float acc[4][4][4] = {};

    load_tile64(Ag, Bg, bm, bn, 0,   K, sbase, 0, tid); CP_COMMIT();
    load_tile64(Ag, Bg, bm, bn, BKt, K, sbase, 1, tid); CP_COMMIT();

    int l8 = lane & 7;
    int aRow  = wm + l8 + ((lane >> 3) & 1) * 8;
    int aCHi  = (lane >> 4) & 1;
    int aXor  = aRow & 7;
    int bRow  = wn + l8 + ((lane >> 4) & 1) * 8;
    int bCHi  = (lane >> 3) & 1;
    int bXor  = bRow & 7;

    // hoisted addressing: row bases (ks-invariant) and xor offsets (4 ks values)
    uint32_t aBase[4], bBase[2], aOff[4], bOff[4];
    #pragma unroll
    for (int mf = 0; mf < 4; mf++) aBase[mf] = (uint32_t)((aRow + mf * 16) * 128);
    #pragma unroll
    for (int g = 0; g < 2; g++)   bBase[g]  = (uint32_t)((bRow + g * 16) * 128) + 16384u;
    #pragma unroll
    for (int ks = 0; ks < 4; ks++) {
        aOff[ks] = (uint32_t)((((ks * 2 + aCHi) ^ aXor) * 16));
        bOff[ks] = (uint32_t)((((ks * 2 + bCHi) ^ bXor) * 16));
    }

    uint32_t af[2][4][4];
    uint32_t bf[2][4][2];

#define FRAGS(buf, sA, ks) do {                                   \
    _Pragma("unroll")                                             \
    for (int mf_ = 0; mf_ < 4; mf_++)                             \
        LDSM_X4(af[buf][mf_], (sA) + aBase[mf_] + aOff[ks]);      \
    _Pragma("unroll")                                             \
    for (int g_ = 0; g_ < 2; g_++) {                              \
        uint32_t r_[4];                                           \
        LDSM_X4(r_, (sA) + bBase[g_] + bOff[ks]);                 \
        bf[buf][2*g_][0] = r_[0]; bf[buf][2*g_][1] = r_[1];       \
        bf[buf][2*g_+1][0] = r_[2]; bf[buf][2*g_+1][1] = r_[3];   \
    }                                                             \
} while (0)

    int cs = 0, ls = 2;
    for (int kk = 0; kk < nkt; kk++) {
        if (kk + 1 < nkt) { CP_WAIT(1); } else { CP_WAIT(0); }
        __syncthreads();

        uint32_t sA = sbase + cs * TILEB;
        if (++cs == STG) cs = 0;

        FRAGS(0, sA, 0);

        if (kk + 2 < nkt) {
            load_tile64(Ag, Bg, bm, bn, (kk + 2) * BKt, K, sbase, ls, tid);
            CP_COMMIT();
            if (++ls == STG) ls = 0;
        }

        #pragma unroll
        for (int ks = 0; ks < 4; ks++) {
            int cur = ks & 1;
            if (ks < 3) FRAGS(cur ^ 1, sA, ks + 1);
            #pragma unroll
            for (int mf = 0; mf < 4; mf++)
                #pragma unroll
                for (int nf = 0; nf < 4; nf++)
                    MMA_F16(acc[mf][nf], af[cur][mf], bf[cur][nf][0], bf[cur][nf][1]);
        }
    }
#undef FRAGS

    // EPI==1: rowinv from partials
    float* invm = reinterpret_cast<float*>(smem);
    if (EPI == 1) {
        __syncthreads();
        if (tid < 128) {
            const float* pp = g_ssqp + (size_t)(bm + tid) * 8;
            float s = pp[0] + pp[1] + pp[2] + pp[3] + pp[4] + pp[5] + pp[6] + pp[7];
            invm[tid] = rsqrtf(s * (1.0f / Cdim) + 1e-6f);
        }
        __syncthreads();
    }

    // epilogue
    int mrow = bm + wm + (lane >> 2);
    int ncol = bn + wn + (lane & 3) * 2;
    float ssA[4] = {0.f, 0.f, 0.f, 0.f};
    float ssB[4] = {0.f, 0.f, 0.f, 0.f};
    #pragma unroll
    for (int mf = 0; mf < 4; mf++) {
        int r0 = mrow + mf * 16;
        float iv0 = 1.f, iv1 = 1.f;
        if (EPI == 1) { iv0 = invm[r0 - bm]; iv1 = invm[r0 - bm + 8]; }
        #pragma unroll
        for (int nf = 0; nf < 4; nf++) {
            int n = ncol + nf * 8;
            float bz0 = bias[n], bz1 = bias[n + 1];
            size_t p0 = (size_t)r0 * N + n;
            size_t p1 = (size_t)(r0 + 8) * N + n;
            if (EPI == 0) {
                float v0 = acc[mf][nf][0] + bz0;
                float v1 = acc[mf][nf][1] + bz1;
                float v2 = acc[mf][nf][2] + bz0;
                float v3 = acc[mf][nf][3] + bz1;
                float2 a0 = *reinterpret_cast<const float2*>(auxF + p0);
                float2 a1 = *reinterpret_cast<const float2*>(auxF + p1);
                v0 = a0.x * (1.f / (1.f + __expf(-v0)));
                v1 = a0.y * (1.f / (1.f + __expf(-v1)));
                v2 = a1.x * (1.f / (1.f + __expf(-v2)));
                v3 = a1.y * (1.f / (1.f + __expf(-v3)));
                __half2 h0, h1;
                h0.x = __float2half(v0); h0.y = __float2half(v1);
                h1.x = __float2half(v2); h1.y = __float2half(v3);
                *reinterpret_cast<__half2*>(outH + p0) = h0;
                *reinterpret_cast<__half2*>(outH + p1) = h1;
                float2 f0 = __half22float2(h0), f1 = __half22float2(h1);
                ssA[mf] += f0.x * f0.x + f0.y * f0.y;
                ssB[mf] += f1.x * f1.x + f1.y * f1.y;
            } else if (EPI == 1) {
                __half2 h0, h1;
                h0.x = __float2half(fmaxf(acc[mf][nf][0] * iv0 + bz0, 0.f));
                h0.y = __float2half(fmaxf(acc[mf][nf][1] * iv0 + bz1, 0.f));
                h1.x = __float2half(fmaxf(acc[mf][nf][2] * iv1 + bz0, 0.f));
                h1.y = __float2half(fmaxf(acc[mf][nf][3] * iv1 + bz1, 0.f));
                *reinterpret_cast<__half2*>(outH + p0) = h0;
                *reinterpret_cast<__half2*>(outH + p1) = h1;
            } else {
                float2 a0 = __half22float2(*reinterpret_cast<const __half2*>(auxH + p0));
                float2 a1 = __half22float2(*reinterpret_cast<const __half2*>(auxH + p1));
                float2 o0; o0.x = acc[mf][nf][0] + bz0 + a0.x; o0.y = acc[mf][nf][1] + bz1 + a0.y;
                float2 o1; o1.x = acc[mf][nf][2] + bz0 + a1.x; o1.y = acc[mf][nf][3] + bz1 + a1.y;
                *reinterpret_cast<float2*>(outF + p0) = o0;
                *reinterpret_cast<float2*>(outF + p1) = o1;
            }
        }
    }

    // EPI==0: reduce ssq -> per-row per-slab partials
    if (EPI == 0) {
        #pragma unroll
        for (int mf = 0; mf < 4; mf++) {
            ssA[mf] += __shfl_xor_sync(0xffffffffu, ssA[mf], 1);
            ssA[mf] += __shfl_xor_sync(0xffffffffu, ssA[mf], 2);
            ssB[mf] += __shfl_xor_sync(0xffffffffu, ssB[mf], 1);
            ssB[mf] += __shfl_xor_sync(0xffffffffu, ssB[mf], 2);
        }
        __syncthreads();
        float* ssm = reinterpret_cast<float*>(smem);
        if ((lane & 3) == 0) {
            int rloc = wm + (lane >> 2);
            #pragma unroll
            for (int mf = 0; mf < 4; mf++) {
                ssm[(rloc + mf * 16) * 4 + (wid & 3)]     = ssA[mf];
                ssm[(rloc + mf * 16 + 8) * 4 + (wid & 3)] = ssB[mf];
            }
        }
        __syncthreads();
        if (tid < 128) {
            float s = ssm[tid * 4] + ssm[tid * 4 + 1] + ssm[tid * 4 + 2] + ssm[tid * 4 + 3];
            g_ssqp[(size_t)(bm + tid) * 8 + blockIdx.x] = s;
        }
    }
}

// ---------------- host ----------------
extern "C" void kernel_launch(void* const* d_in, const int* in_sizes, int n_in,
                              void* d_out, int out_size)
{
    const float* x   = (const float*)d_in[0];
    const float* n1w = (const float*)d_in[1];
    const float* w1  = (const float*)d_in[2];
    const float* b1  = (const float*)d_in[3];
    const float* n2w = (const float*)d_in[4];
    const float* w2a = (const float*)d_in[5];
    const float* b2a = (const float*)d_in[6];
    const float* w2b = (const float*)d_in[7];
    const float* b2b = (const float*)d_in[8];
    float* out = (float*)d_out;

    void *p_s, *p_a, *p_w1, *p_w2a, *p_w2b, *p_o1, *p_fl;
    cudaGetSymbolAddress(&p_s, g_s);
    cudaGetSymbolAddress(&p_a, g_act);
    cudaGetSymbolAddress(&p_w1, g_w1T);
    cudaGetSymbolAddress(&p_w2a, g_w2aT);
    cudaGetSymbolAddress(&p_w2b, g_w2bT);
    cudaGetSymbolAddress(&p_o1, g_out1);
    cudaGetSymbolAddress(&p_fl, g_flag);

    cudaFuncSetAttribute(mma_gemm<0>, cudaFuncAttributeMaxDynamicSharedMemorySize, SMTOT);
    cudaFuncSetAttribute(mma_gemm<1>, cudaFuncAttributeMaxDynamicSharedMemorySize, SMTOT);
    cudaFuncSetAttribute(mma_gemm<2>, cudaFuncAttributeMaxDynamicSharedMemorySize, SMTOT);
    cudaFuncSetAttribute(scan_fused, cudaFuncAttributeMaxDynamicSharedMemorySize, SCAN_SMEM);

    // persistent streams + events
    static cudaStream_t s_w = nullptr, s_p1 = nullptr;
    static cudaEvent_t ev_fork = nullptr, ev_w = nullptr, ev_p1 = nullptr;
    if (!s_w) {
        cudaStreamCreateWithFlags(&s_w,  cudaStreamNonBlocking);
        cudaStreamCreateWithFlags(&s_p1, cudaStreamNonBlocking);
        cudaEventCreateWithFlags(&ev_fork, cudaEventDisableTiming);
        cudaEventCreateWithFlags(&ev_w,    cudaEventDisableTiming);
        cudaEventCreateWithFlags(&ev_p1,   cudaEventDisableTiming);
    }

    // fork point
    cudaEventRecord(ev_fork, 0);

    // weight stream: transposes (shared by both pipelines)
    cudaStreamWaitEvent(s_w, ev_fork, 0);
    trans_kernel<<<TW1 + TW2A + TW2B, 256, 0, s_w>>>(w1, w2a, n2w, w2b);
    cudaEventRecord(ev_w, s_w);

    const f16* S  = (const f16*)p_s;
    const f16* W1 = (const f16*)p_w1;
    const f16* W2A = (const f16*)p_w2a;
    const f16* W2B = (const f16*)p_w2b;
    f16* O1 = (f16*)p_o1;
    f16* ACT = (f16*)p_a;

    // ---- pipeline 1 (batches 4..7, rows 8192..16383) on s_p1 ----
    cudaStreamWaitEvent(s_p1, ev_fork, 0);
    cudaMemsetAsync((int*)p_fl + BHALF * NCHUNK, 0, BHALF * NCHUNK * sizeof(int), s_p1);
    scan_fused<<<dim3(NCHUNK, BHALF), 256, SCAN_SMEM, s_p1>>>(x, n1w, BHALF);
    cudaStreamWaitEvent(s_p1, ev_w, 0);
    mma_gemm<0><<<dim3(Cdim / 128, MHALF / 128), 256, SMTOT, s_p1>>>(
        S, W1, b1, x, nullptr, nullptr, O1, Cdim, Cdim, MHALF);
    mma_gemm<1><<<dim3(Edim / 128, MHALF / 128), 256, SMTOT, s_p1>>>(
        O1, W2A, b2a, nullptr, nullptr, nullptr, ACT, Edim, Cdim, MHALF);
    mma_gemm<2><<<dim3(Cdim / 128, MHALF / 128), 256, SMTOT, s_p1>>>(
        ACT, W2B, b2b, nullptr, O1, out, nullptr, Cdim, Edim, MHALF);
    cudaEventRecord(ev_p1, s_p1);

    // ---- pipeline 0 (batches 0..3, rows 0..8191) on default stream ----
    cudaMemsetAsync((int*)p_fl, 0, BHALF * NCHUNK * sizeof(int), 0);
    scan_fused<<<dim3(NCHUNK, BHALF), 256, SCAN_SMEM>>>(x, n1w, 0);
    cudaStreamWaitEvent(0, ev_w, 0);
    mma_gemm<0><<<dim3(Cdim / 128, MHALF / 128), 256, SMTOT>>>(
        S, W1, b1, x, nullptr, nullptr, O1, Cdim, Cdim, 0);
    mma_gemm<1><<<dim3(Edim / 128, MHALF / 128), 256, SMTOT>>>(
        O1, W2A, b2a, nullptr, nullptr, nullptr, ACT, Edim, Cdim, 0);
    mma_gemm<2><<<dim3(Cdim / 128, MHALF / 128), 256, SMTOT>>>(
        ACT, W2B, b2b, nullptr, O1, out, nullptr, Cdim, Edim, 0);

    // join
    cudaStreamWaitEvent(0, ev_p1, 0);
}

// round 16
// speedup vs baseline: 1.1028x; 1.1028x over previous
#include <cuda_runtime.h>
#include <cuda.h>
#include <cuda_fp16.h>
#include <math.h>
#include <stdint.h>

#define Bsz   8
#define Tlen  2048
#define Cdim  1024
#define Edim  4096
#define Mtot  (Bsz * Tlen)       // 16384 tokens
#define CHUNK 32
#define NCHUNK (Tlen / CHUNK)    // 64
#define BHALF (Bsz / 2)          // 4 batches per pipeline
#define MHALF (Mtot / 2)         // 8192 rows per pipeline

typedef __half f16;

// ---------------- scratch (no cudaMalloc allowed) ----------------
__device__ __align__(16) f16   g_out1[(size_t)Mtot * Cdim];   // gate*x (fp16 residual)
__device__ __align__(16) float g_csum[Bsz * NCHUNK * Cdim];   // chunk aggregates
__device__ __align__(16) int   g_flag[Bsz * NCHUNK];          // aggregate-published flags
__device__ __align__(16) float g_ssqp[(size_t)Mtot * 8];      // per-row ssq partials (8 slabs)

__device__ __align__(16) f16 g_s  [(size_t)Mtot * Cdim];   // state (fp16)
__device__ __align__(16) f16 g_act[(size_t)Mtot * Edim];   // relu hidden (fp16)

// transposed weights: [N, K] K-major fp16
__device__ __align__(16) f16 g_w1T [Cdim * Cdim];
__device__ __align__(16) f16 g_w2aT[(size_t)Edim * Cdim];  // includes n2w fold
__device__ __align__(16) f16 g_w2bT[(size_t)Cdim * Edim];

// ---------------- helpers ----------------
__device__ __forceinline__ uint32_t smem_u32(const void* p) {
    uint32_t a;
    asm("{ .reg .u64 t; cvta.to.shared.u64 t, %1; cvt.u32.u64 %0, t; }" : "=r"(a) : "l"(p));
    return a;
}
__device__ __forceinline__ void cp16(uint32_t s, const void* g) {
    asm volatile("cp.async.cg.shared.global [%0], [%1], 16;" :: "r"(s), "l"(g) : "memory");
}
#define CP_COMMIT() asm volatile("cp.async.commit_group;" ::: "memory")
#define CP_WAIT(n)  asm volatile("cp.async.wait_group %0;" :: "n"(n) : "memory")

#define LDSM_X4(r, addr) \
    asm volatile("ldmatrix.sync.aligned.m8n8.x4.shared.b16 {%0,%1,%2,%3}, [%4];" \
        : "=r"((r)[0]), "=r"((r)[1]), "=r"((r)[2]), "=r"((r)[3]) : "r"(addr))

#define MMA_F16(d, a, b0, b1) \
    asm volatile("mma.sync.aligned.m16n8k16.row.col.f32.f16.f16.f32 " \
        "{%0,%1,%2,%3}, {%4,%5,%6,%7}, {%8,%9}, {%0,%1,%2,%3};" \
        : "+f"((d)[0]), "+f"((d)[1]), "+f"((d)[2]), "+f"((d)[3]) \
        : "r"((a)[0]), "r"((a)[1]), "r"((a)[2]), "r"((a)[3]), "r"(b0), "r"(b1))

// ---------------- fused rmsnorm1 + full scan (decoupled lookback) ----------------
#define SCAN_SMEM (65536 + 32768)   // ys 32x1024 f16 (64KB) + sacc 8x1024 f32 (32KB)

__global__ void __launch_bounds__(256) scan_fused(const float* __restrict__ x,
                                                  const float* __restrict__ w,
                                                  int b0)
{
    extern __shared__ __align__(16) char sm[];
    f16*   ys   = reinterpret_cast<f16*>(sm);            // [32][1024]
    float* sacc = reinterpret_cast<float*>(sm + 65536);  // [8][1024]

    int ch = blockIdx.x, b = b0 + blockIdx.y;
    int tid = threadIdx.x, wid = tid >> 5, lane = tid & 31;
    int R0 = b * Tlen + ch * CHUNK;

    float4 acc[8];
    #pragma unroll
    for (int j = 0; j < 8; j++) acc[j] = make_float4(0.f, 0.f, 0.f, 0.f);

    #pragma unroll
    for (int r = 0; r < 4; r++) {
        int rloc = wid * 4 + r;
        const float4* xr = reinterpret_cast<const float4*>(x) + (size_t)(R0 + rloc) * (Cdim / 4);
        float4 v[8];
        #pragma unroll
        for (int j = 0; j < 8; j++) v[j] = xr[lane + 32 * j];
        float ss = 0.f;
        #pragma unroll
        for (int j = 0; j < 8; j++)
            ss += v[j].x * v[j].x + v[j].y * v[j].y + v[j].z * v[j].z + v[j].w * v[j].w;
        #pragma unroll
        for (int o = 16; o; o >>= 1) ss += __shfl_xor_sync(0xffffffffu, ss, o);
        float inv = rsqrtf(ss * (1.0f / Cdim) + 1e-6f);

        #pragma unroll
        for (int j = 0; j < 8; j++) {
            float4 wv = reinterpret_cast<const float4*>(w)[lane + 32 * j];
            __half2 ha, hb;
            ha.x = __float2half(v[j].x * inv * wv.x);
            ha.y = __float2half(v[j].y * inv * wv.y);
            hb.x = __float2half(v[j].z * inv * wv.z);
            hb.y = __float2half(v[j].w * inv * wv.w);
            uint2 pk;
            pk.x = *reinterpret_cast<const unsigned*>(&ha);
            pk.y = *reinterpret_cast<const unsigned*>(&hb);
            *reinterpret_cast<uint2*>(ys + (size_t)rloc * Cdim + (lane + 32 * j) * 4) = pk;
            float2 fa = __half22float2(ha), fb = __half22float2(hb);
            acc[j].x += fa.x; acc[j].y += fa.y; acc[j].z += fb.x; acc[j].w += fb.y;
        }
    }

    #pragma unroll
    for (int j = 0; j < 8; j++)
        *reinterpret_cast<float4*>(&sacc[wid * 1024 + (lane + 32 * j) * 4]) = acc[j];
    __syncthreads();
    float4 aggv = make_float4(0.f, 0.f, 0.f, 0.f);
    #pragma unroll
    for (int w8 = 0; w8 < 8; w8++) {
        float4 t = *reinterpret_cast<const float4*>(&sacc[w8 * 1024 + tid * 4]);
        aggv.x += t.x; aggv.y += t.y; aggv.z += t.z; aggv.w += t.w;
    }

    float4* csum4 = reinterpret_cast<float4*>(g_csum);
    csum4[(size_t)(b * NCHUNK + ch) * 256 + tid] = aggv;
    __threadfence();
    __syncthreads();
    if (tid == 0) atomicExch(&g_flag[b * NCHUNK + ch], 1);

    float4 run = make_float4(0.f, 0.f, 0.f, 0.f);
    if (ch > 0) {
        volatile int* fl = (volatile int*)(g_flag + b * NCHUNK);
        bool all;
        do {
            bool mine = (tid < ch) ? (fl[tid] != 0) : true;
            all = __syncthreads_and(mine);
        } while (!all);
        __threadfence();
        const float4* aggp = csum4 + (size_t)b * NCHUNK * 256 + tid;
        for (int j = 0; j < ch; j++) {
            float4 a;
            const float4* p = aggp + (size_t)j * 256;
            asm volatile("ld.global.cg.v4.f32 {%0,%1,%2,%3}, [%4];"
                         : "=f"(a.x), "=f"(a.y), "=f"(a.z), "=f"(a.w) : "l"(p));
            run.x += a.x; run.y += a.y; run.z += a.z; run.w += a.w;
        }
    }

    int tg0 = ch * CHUNK;
    #pragma unroll
    for (int t = 0; t < CHUNK; t++) {
        uint2 pk = *reinterpret_cast<const uint2*>(ys + (size_t)t * Cdim + tid * 4);
        __half2 ha = *reinterpret_cast<const __half2*>(&pk.x);
        __half2 hb = *reinterpret_cast<const __half2*>(&pk.y);
        float2 fa = __half22float2(ha), fb = __half22float2(hb);
        run.x += fa.x; run.y += fa.y; run.z += fb.x; run.w += fb.y;
        float tg = (float)(tg0 + t);
        float rs = 1.0f / (0.5f * (tg + 1.f) * (tg + 2.f));
        __half2 o0, o1;
        o0.x = __float2half(run.x * rs); o0.y = __float2half(run.y * rs);
        o1.x = __float2half(run.z * rs); o1.y = __float2half(run.w * rs);
        uint2 ow;
        ow.x = *reinterpret_cast<const unsigned*>(&o0);
        ow.y = *reinterpret_cast<const unsigned*>(&o1);
        *reinterpret_cast<uint2*>(g_s + (size_t)(R0 + t) * Cdim + tid * 4) = ow;
    }
}

// ---------------- weight transposes (side stream) ----------------
__device__ __forceinline__ void transpose_tile(const float* __restrict__ in,
                                               f16* __restrict__ o16,
                                               const float* __restrict__ scale,
                                               int K, int N, int bx, int by, float* sh)
{
    int k0 = bx * 32, n0 = by * 32;
    int x = threadIdx.x & 31, y = threadIdx.x >> 5;
    #pragma unroll
    for (int i = y; i < 32; i += 8)
        sh[i * 33 + x] = in[(size_t)(k0 + i) * N + n0 + x];
    __syncthreads();
    float sc = scale ? scale[k0 + x] : 1.0f;
    #pragma unroll
    for (int i = y; i < 32; i += 8)
        o16[(size_t)(n0 + i) * K + k0 + x] = __float2half(sh[x * 33 + i] * sc);
}

#define TW1  (Cdim / 32) * (Cdim / 32)   // 1024
#define TW2A (Cdim / 32) * (Edim / 32)   // 4096
#define TW2B (Edim / 32) * (Cdim / 32)   // 4096

__global__ void __launch_bounds__(256) trans_kernel(const float* __restrict__ w1,
                                                    const float* __restrict__ w2a,
                                                    const float* __restrict__ n2w,
                                                    const float* __restrict__ w2b)
{
    __shared__ float sh[32 * 33];
    int bid = blockIdx.x;
    if (bid < TW1)  { transpose_tile(w1,  g_w1T,  nullptr, Cdim, Cdim, bid & 31, bid >> 5, sh); return; }
    bid -= TW1;
    if (bid < TW2A) { transpose_tile(w2a, g_w2aT, n2w, Cdim, Edim, bid & 31, bid >> 5, sh); return; }
    bid -= TW2A;
    transpose_tile(w2b, g_w2bT, nullptr, Edim, Cdim, bid & 127, bid >> 7, sh);
}

// ---------------- fp16 HMMA GEMM: 128x128x64 tiles, 3-stage cp.async ----------------
// EPI 0: outH = (f16)(sigmoid(acc+bias) * auxF); also writes per-row ssq partials
// EPI 1: outH = (f16) relu(acc*rowinv[m] + bias)   (rowinv from g_ssqp partials)
// EPI 2: outF = acc + bias + auxH (fp16 residual)
#define BKt    64
#define STG    3
#define TILEB  32768
#define SMTOT  (STG * TILEB)

__device__ __forceinline__ void load_tile64(const f16* __restrict__ A,
                                            const f16* __restrict__ B,
                                            int bm, int bn, int koff, int K,
                                            uint32_t sbase, int stage, int tid)
{
    uint32_t sA = sbase + stage * TILEB;
    uint32_t sB = sA + 16384;
    #pragma unroll
    for (int i = 0; i < 4; i++) {
        int idx = tid + i * 256;
        int row = idx >> 3, ch = idx & 7;
        int chs = ch ^ (row & 7);
        uint32_t so = (uint32_t)(row * 128 + chs * 16);
        cp16(sA + so, A + (size_t)(bm + row) * K + koff + ch * 8);
        cp16(sB + so, B + (size_t)(bn + row) * K + koff + ch * 8);
    }
}

template<int EPI>
__global__ void __launch_bounds__(256, 2) mma_gemm(
    const f16* __restrict__ Ag, const f16* __restrict__ Bg,
    const float* __restrict__ bias,
    const float* __restrict__ auxF, const f16* __restrict__ auxH,
    float* __restrict__ outF, f16* __restrict__ outH,
    int N, int K, int bmOff)
{
    extern __shared__ __align__(16) char smem[];
    uint32_t sbase = smem_u32(smem);
    int tid = threadIdx.x, wid = tid >> 5, lane = tid & 31;
    int bm = bmOff + blockIdx.y * 128, bn = blockIdx.x * 128;
    int wm = (wid >> 2) * 64, wn = (wid & 3) * 32;

    int nkt = K / BKt;

    float acc[4][4][4] = {};

    load_tile64(Ag, Bg, bm, bn, 0,   K, sbase, 0, tid); CP_COMMIT();
    load_tile64(Ag, Bg, bm, bn, BKt, K, sbase, 1, tid); CP_COMMIT();

    int l8 = lane & 7;
    int aRow  = wm + l8 + ((lane >> 3) & 1) * 8;
    int aCHi  = (lane >> 4) & 1;
    int aXor  = aRow & 7;
    int bRow  = wn + l8 + ((lane >> 4) & 1) * 8;
    int bCHi  = (lane >> 3) & 1;
    int bXor  = bRow & 7;

    int cs = 0, ls = 2;
    for (int kk = 0; kk < nkt; kk++) {
        if (kk + 1 < nkt) { CP_WAIT(1); } else { CP_WAIT(0); }
        __syncthreads();

        if (kk + 2 < nkt) {
            load_tile64(Ag, Bg, bm, bn, (kk + 2) * BKt, K, sbase, ls, tid);
            CP_COMMIT();
            if (++ls == STG) ls = 0;
        }

        uint32_t sA = sbase + cs * TILEB;
        uint32_t sB = sA + 16384;
        if (++cs == STG) cs = 0;

        #pragma unroll
        for (int ks = 0; ks < 4; ks++) {
            uint32_t a[4][4];
            uint32_t b[4][2];
            // A[0] first, then B groups, then A[1..3]: the mf=0 MMA quartet's
            // operands are ready after the 3rd LDSM, overlapping A1-A3 latency.
            {
                uint32_t addr = sA + (uint32_t)((aRow) * 128
                              + (((ks * 2 + aCHi) ^ aXor) * 16));
                LDSM_X4(a[0], addr);
            }
            #pragma unroll
            for (int g = 0; g < 2; g++) {
                uint32_t r[4];
                uint32_t addr = sB + (uint32_t)((bRow + g * 16) * 128
                              + (((ks * 2 + bCHi) ^ bXor) * 16));
                LDSM_X4(r, addr);
                b[2*g][0] = r[0]; b[2*g][1] = r[1];
                b[2*g+1][0] = r[2]; b[2*g+1][1] = r[3];
            }
            #pragma unroll
            for (int mf = 1; mf < 4; mf++) {
                uint32_t addr = sA + (uint32_t)((aRow + mf * 16) * 128
                              + (((ks * 2 + aCHi) ^ aXor) * 16));
                LDSM_X4(a[mf], addr);
            }
            #pragma unroll
            for (int mf = 0; mf < 4; mf++)
                #pragma unroll
                for (int nf = 0; nf < 4; nf++)
                    MMA_F16(acc[mf][nf], a[mf], b[nf][0], b[nf][1]);
        }
    }

    // EPI==1: rowinv from partials
    float* invm = reinterpret_cast<float*>(smem);
    if (EPI == 1) {
        __syncthreads();
        if (tid < 128) {
            const float* pp = g_ssqp + (size_t)(bm + tid) * 8;
            float s = pp[0] + pp[1] + pp[2] + pp[3] + pp[4] + pp[5] + pp[6] + pp[7];
            invm[tid] = rsqrtf(s * (1.0f / Cdim) + 1e-6f);
        }
        __syncthreads();
    }

    // epilogue
    int mrow = bm + wm + (lane >> 2);
    int ncol = bn + wn + (lane & 3) * 2;
    float ssA[4] = {0.f, 0.f, 0.f, 0.f};
    float ssB[4] = {0.f, 0.f, 0.f, 0.f};
    #pragma unroll
    for (int mf = 0; mf < 4; mf++) {
        int r0 = mrow + mf * 16;
        float iv0 = 1.f, iv1 = 1.f;
        if (EPI == 1) { iv0 = invm[r0 - bm]; iv1 = invm[r0 - bm + 8]; }
        #pragma unroll
        for (int nf = 0; nf < 4; nf++) {
            int n = ncol + nf * 8;
            float bz0 = bias[n], bz1 = bias[n + 1];
            size_t p0 = (size_t)r0 * N + n;
            size_t p1 = (size_t)(r0 + 8) * N + n;
            if (EPI == 0) {
                float v0 = acc[mf][nf][0] + bz0;
                float v1 = acc[mf][nf][1] + bz1;
                float v2 = acc[mf][nf][2] + bz0;
                float v3 = acc[mf][nf][3] + bz1;
                float2 a0 = *reinterpret_cast<const float2*>(auxF + p0);
                float2 a1 = *reinterpret_cast<const float2*>(auxF + p1);
                v0 = a0.x * (1.f / (1.f + __expf(-v0)));
                v1 = a0.y * (1.f / (1.f + __expf(-v1)));
                v2 = a1.x * (1.f / (1.f + __expf(-v2)));
                v3 = a1.y * (1.f / (1.f + __expf(-v3)));
                __half2 h0, h1;
                h0.x = __float2half(v0); h0.y = __float2half(v1);
                h1.x = __float2half(v2); h1.y = __float2half(v3);
                *reinterpret_cast<__half2*>(outH + p0) = h0;
                *reinterpret_cast<__half2*>(outH + p1) = h1;
                float2 f0 = __half22float2(h0), f1 = __half22float2(h1);
                ssA[mf] += f0.x * f0.x + f0.y * f0.y;
                ssB[mf] += f1.x * f1.x + f1.y * f1.y;
            } else if (EPI == 1) {
                __half2 h0, h1;
                h0.x = __float2half(fmaxf(acc[mf][nf][0] * iv0 + bz0, 0.f));
                h0.y = __float2half(fmaxf(acc[mf][nf][1] * iv0 + bz1, 0.f));
                h1.x = __float2half(fmaxf(acc[mf][nf][2] * iv1 + bz0, 0.f));
                h1.y = __float2half(fmaxf(acc[mf][nf][3] * iv1 + bz1, 0.f));
                *reinterpret_cast<__half2*>(outH + p0) = h0;
                *reinterpret_cast<__half2*>(outH + p1) = h1;
            } else {
                float2 a0 = __half22float2(*reinterpret_cast<const __half2*>(auxH + p0));
                float2 a1 = __half22float2(*reinterpret_cast<const __half2*>(auxH + p1));
                float2 o0; o0.x = acc[mf][nf][0] + bz0 + a0.x; o0.y = acc[mf][nf][1] + bz1 + a0.y;
                float2 o1; o1.x = acc[mf][nf][2] + bz0 + a1.x; o1.y = acc[mf][nf][3] + bz1 + a1.y;
                *reinterpret_cast<float2*>(outF + p0) = o0;
                *reinterpret_cast<float2*>(outF + p1) = o1;
            }
        }
    }

    // EPI==0: reduce ssq -> per-row per-slab partials
    if (EPI == 0) {
        #pragma unroll
        for (int mf = 0; mf < 4; mf++) {
            ssA[mf] += __shfl_xor_sync(0xffffffffu, ssA[mf], 1);
            ssA[mf] += __shfl_xor_sync(0xffffffffu, ssA[mf], 2);
            ssB[mf] += __shfl_xor_sync(0xffffffffu, ssB[mf], 1);
            ssB[mf] += __shfl_xor_sync(0xffffffffu, ssB[mf], 2);
        }
        __syncthreads();
        float* ssm = reinterpret_cast<float*>(smem);
        if ((lane & 3) == 0) {
            int rloc = wm + (lane >> 2);
            #pragma unroll
            for (int mf = 0; mf < 4; mf++) {
                ssm[(rloc + mf * 16) * 4 + (wid & 3)]     = ssA[mf];
                ssm[(rloc + mf * 16 + 8) * 4 + (wid & 3)] = ssB[mf];
            }
        }
        __syncthreads();
        if (tid < 128) {
            float s = ssm[tid * 4] + ssm[tid * 4 + 1] + ssm[tid * 4 + 2] + ssm[tid * 4 + 3];
            g_ssqp[(size_t)(bm + tid) * 8 + blockIdx.x] = s;
        }
    }
}

// ---------------- host ----------------
extern "C" void kernel_launch(void* const* d_in, const int* in_sizes, int n_in,
                              void* d_out, int out_size)
{
    const float* x   = (const float*)d_in[0];
    const float* n1w = (const float*)d_in[1];
    const float* w1  = (const float*)d_in[2];
    const float* b1  = (const float*)d_in[3];
    const float* n2w = (const float*)d_in[4];
    const float* w2a = (const float*)d_in[5];
    const float* b2a = (const float*)d_in[6];
    const float* w2b = (const float*)d_in[7];
    const float* b2b = (const float*)d_in[8];
    float* out = (float*)d_out;

    void *p_s, *p_a, *p_w1, *p_w2a, *p_w2b, *p_o1, *p_fl;
    cudaGetSymbolAddress(&p_s, g_s);
    cudaGetSymbolAddress(&p_a, g_act);
    cudaGetSymbolAddress(&p_w1, g_w1T);
    cudaGetSymbolAddress(&p_w2a, g_w2aT);
    cudaGetSymbolAddress(&p_w2b, g_w2bT);
    cudaGetSymbolAddress(&p_o1, g_out1);
    cudaGetSymbolAddress(&p_fl, g_flag);

    cudaFuncSetAttribute(mma_gemm<0>, cudaFuncAttributeMaxDynamicSharedMemorySize, SMTOT);
    cudaFuncSetAttribute(mma_gemm<1>, cudaFuncAttributeMaxDynamicSharedMemorySize, SMTOT);
    cudaFuncSetAttribute(mma_gemm<2>, cudaFuncAttributeMaxDynamicSharedMemorySize, SMTOT);
    cudaFuncSetAttribute(scan_fused, cudaFuncAttributeMaxDynamicSharedMemorySize, SCAN_SMEM);

    // persistent streams + events
    static cudaStream_t s_w = nullptr, s_p1 = nullptr;
    static cudaEvent_t ev_fork = nullptr, ev_w = nullptr, ev_p1 = nullptr;
    if (!s_w) {
        cudaStreamCreateWithFlags(&s_w,  cudaStreamNonBlocking);
        cudaStreamCreateWithFlags(&s_p1, cudaStreamNonBlocking);
        cudaEventCreateWithFlags(&ev_fork, cudaEventDisableTiming);
        cudaEventCreateWithFlags(&ev_w,    cudaEventDisableTiming);
        cudaEventCreateWithFlags(&ev_p1,   cudaEventDisableTiming);
    }

    // fork point
    cudaEventRecord(ev_fork, 0);

    // weight stream: transposes (shared by both pipelines)
    cudaStreamWaitEvent(s_w, ev_fork, 0);
    trans_kernel<<<TW1 + TW2A + TW2B, 256, 0, s_w>>>(w1, w2a, n2w, w2b);
    cudaEventRecord(ev_w, s_w);

    const f16* S  = (const f16*)p_s;
    const f16* W1 = (const f16*)p_w1;
    const f16* W2A = (const f16*)p_w2a;
    const f16* W2B = (const f16*)p_w2b;
    f16* O1 = (f16*)p_o1;
    f16* ACT = (f16*)p_a;

    // ---- pipeline 1 (batches 4..7, rows 8192..16383) on s_p1 ----
    cudaStreamWaitEvent(s_p1, ev_fork, 0);
    cudaMemsetAsync((int*)p_fl + BHALF * NCHUNK, 0, BHALF * NCHUNK * sizeof(int), s_p1);
    scan_fused<<<dim3(NCHUNK, BHALF), 256, SCAN_SMEM, s_p1>>>(x, n1w, BHALF);
    cudaStreamWaitEvent(s_p1, ev_w, 0);
    mma_gemm<0><<<dim3(Cdim / 128, MHALF / 128), 256, SMTOT, s_p1>>>(
        S, W1, b1, x, nullptr, nullptr, O1, Cdim, Cdim, MHALF);
    mma_gemm<1><<<dim3(Edim / 128, MHALF / 128), 256, SMTOT, s_p1>>>(
        O1, W2A, b2a, nullptr, nullptr, nullptr, ACT, Edim, Cdim, MHALF);
    mma_gemm<2><<<dim3(Cdim / 128, MHALF / 128), 256, SMTOT, s_p1>>>(
        ACT, W2B, b2b, nullptr, O1, out, nullptr, Cdim, Edim, MHALF);
    cudaEventRecord(ev_p1, s_p1);

    // ---- pipeline 0 (batches 0..3, rows 0..8191) on default stream ----
    cudaMemsetAsync((int*)p_fl, 0, BHALF * NCHUNK * sizeof(int), 0);
    scan_fused<<<dim3(NCHUNK, BHALF), 256, SCAN_SMEM>>>(x, n1w, 0);
    cudaStreamWaitEvent(0, ev_w, 0);
    mma_gemm<0><<<dim3(Cdim / 128, MHALF / 128), 256, SMTOT>>>(
        S, W1, b1, x, nullptr, nullptr, O1, Cdim, Cdim, 0);
    mma_gemm<1><<<dim3(Edim / 128, MHALF / 128), 256, SMTOT>>>(
        O1, W2A, b2a, nullptr, nullptr, nullptr, ACT, Edim, Cdim, 0);
    mma_gemm<2><<<dim3(Cdim / 128, MHALF / 128), 256, SMTOT>>>(
        ACT, W2B, b2b, nullptr, O1, out, nullptr, Cdim, Edim, 0);

    // join
    cudaStreamWaitEvent(0, ev_p1, 0);
}